// round 8
// baseline (speedup 1.0000x reference)
#include <cuda_runtime.h>

// Fused 5-point replicate-pad stencil + cubic Horner polynomial.
// R8: persistent CTAs (grid-stride over row-quads) — one wave, no wave
// transition overhead. Body = proven RPT=4 path (1.5 row-loads/output,
// halo via warp shuffle, streaming stores).

#define H_DIM   2048
#define W_DIM   2048
#define W4      (W_DIM / 4)     // 512 float4 per row
#define RPT     4               // rows per thread
#define HQ      (H_DIM / RPT)   // 512 row-quads per plane
#define NBLK    740             // 148 SMs * 5 CTAs (48 regs -> 5 fit)

__global__ void __launch_bounds__(256, 5) stencil_poly_pers(
    const float* __restrict__ x,
    const float* __restrict__ a,
    const float* __restrict__ w,
    float* __restrict__ out,
    int nplanes)
{
    // tiles: one tile = 256 threads covering half a row-quad (256 float4).
    // tiles per plane = HQ * (W4/256) = 512*2 = 1024.
    const int tiles_per_plane = HQ * (W4 / 256);
    const int total_tiles = nplanes * tiles_per_plane;

    int lane = threadIdx.x & 31;

    float a0 = __ldg(a + 0), a1 = __ldg(a + 1), a2 = __ldg(a + 2);
    float w0 = __ldg(w + 0), w1 = __ldg(w + 1), w2 = __ldg(w + 2), w3 = __ldg(w + 3);

    for (int tile = blockIdx.x; tile < total_tiles; tile += NBLK) {
        // decode tile -> (plane, row-quad, half) ; all pow2 -> shifts/masks
        int p    = tile >> 10;             // / 1024
        int rem  = tile & 1023;
        int rq   = rem >> 1;               // row-quad index
        int half = rem & 1;

        int c4 = (half << 8) + threadIdx.x;   // 0..511
        int rbase = rq << 2;

        int plane_off = p * (H_DIM * W_DIM);
        const float* plane = x + plane_off;

        int rtop = (rbase > 0) ? rbase - 1 : 0;
        int rbot = (rbase + 4 < H_DIM) ? rbase + 4 : H_DIM - 1;

        // 6 front-batched row loads
        float4 v[6];
        v[0] = __ldg((const float4*)(plane + rtop        * W_DIM) + c4);
        v[1] = __ldg((const float4*)(plane + (rbase    ) * W_DIM) + c4);
        v[2] = __ldg((const float4*)(plane + (rbase + 1) * W_DIM) + c4);
        v[3] = __ldg((const float4*)(plane + (rbase + 2) * W_DIM) + c4);
        v[4] = __ldg((const float4*)(plane + (rbase + 3) * W_DIM) + c4);
        v[5] = __ldg((const float4*)(plane + rbot        * W_DIM) + c4);

        // horizontal halo via shuffle (warps row-aligned: 512 % 32 == 0)
        int c = c4 << 2;
        float lh[RPT], rh[RPT];
        #pragma unroll
        for (int i = 0; i < RPT; i++) {
            lh[i] = __shfl_up_sync  (0xFFFFFFFFu, v[i + 1].w, 1);
            rh[i] = __shfl_down_sync(0xFFFFFFFFu, v[i + 1].x, 1);
        }
        if (lane == 0) {
            #pragma unroll
            for (int i = 0; i < RPT; i++) {
                const float* row = plane + (rbase + i) * W_DIM;
                lh[i] = (c == 0) ? v[i + 1].x : __ldg(row + c - 1);
            }
        }
        if (lane == 31) {
            #pragma unroll
            for (int i = 0; i < RPT; i++) {
                const float* row = plane + (rbase + i) * W_DIM;
                rh[i] = (c + 4 == W_DIM) ? v[i + 1].w : __ldg(row + c + 4);
            }
        }

        float* oplane = out + plane_off;

        #pragma unroll
        for (int i = 0; i < RPT; i++) {
            float4 cv = v[i + 1];
            float4 up = v[i];
            float4 dn = v[i + 2];
            float4 o;

            float xv = cv.x;
            o.x = a0*xv + a1*(lh[i] + cv.y) + a2*(up.x + dn.x)
                + fmaf(fmaf(fmaf(w3, xv, w2), xv, w1), xv, w0);
            xv = cv.y;
            o.y = a0*xv + a1*(cv.x + cv.z) + a2*(up.y + dn.y)
                + fmaf(fmaf(fmaf(w3, xv, w2), xv, w1), xv, w0);
            xv = cv.z;
            o.z = a0*xv + a1*(cv.y + cv.w) + a2*(up.z + dn.z)
                + fmaf(fmaf(fmaf(w3, xv, w2), xv, w1), xv, w0);
            xv = cv.w;
            o.w = a0*xv + a1*(cv.z + rh[i]) + a2*(up.w + dn.w)
                + fmaf(fmaf(fmaf(w3, xv, w2), xv, w1), xv, w0);

            __stcs((float4*)(oplane + (rbase + i) * W_DIM) + c4, o);
        }
    }
}

extern "C" void kernel_launch(void* const* d_in, const int* in_sizes, int n_in,
                              void* d_out, int out_size)
{
    const float* x = (const float*)d_in[0];
    const float* a = (const float*)d_in[1];
    const float* w = (const float*)d_in[2];
    float* out = (float*)d_out;

    int n = in_sizes[0];
    int nplanes = n / (H_DIM * W_DIM);  // B*C = 16

    stencil_poly_pers<<<NBLK, 256>>>(x, a, w, out, nplanes);
}

// round 9
// speedup vs baseline: 1.1906x; 1.1906x over previous
#include <cuda_runtime.h>

// Fused 5-point replicate-pad stencil + cubic Horner polynomial.
// R9 = R4 (session best, 80.5us): 4 rows per thread — 6 row-loads produce
// 4 outputs (1.5 loads/output), MLP_p1=6 front-batched LDG.128, streaming
// stores. Confirmed optimal operating point: R5/R6 (deeper blocking),
// R7 (3D grid), R8 (persistent) were all neutral-or-worse; memory system
// saturates ~6.2 TB/s for this mixed r/w stream at minimum traffic.

#define H_DIM 2048
#define W_DIM 2048

__global__ void __launch_bounds__(256) stencil_poly_4row(
    const float* __restrict__ x,
    const float* __restrict__ a,
    const float* __restrict__ w,
    float* __restrict__ out,
    int nplanes)
{
    const int W4 = W_DIM >> 2;      // 512
    const int HQ = H_DIM >> 2;      // 512 row-quads

    long long tid = (long long)blockIdx.x * blockDim.x + threadIdx.x;
    long long total = (long long)nplanes * HQ * W4;
    if (tid >= total) return;

    int c4 = (int)(tid % W4);
    long long t2 = tid / W4;
    int rq = (int)(t2 % HQ);
    int p  = (int)(t2 / HQ);

    int rbase = rq << 2;            // first of 4 rows

    const float* plane = x + (long long)p * H_DIM * W_DIM;

    // 6 row loads: rbase-1 .. rbase+4, clamped at plane edges.
    int rtop = (rbase > 0) ? rbase - 1 : 0;
    int rbot = (rbase + 4 < H_DIM) ? rbase + 4 : H_DIM - 1;

    float4 v[6];
    v[0] = __ldg((const float4*)(plane + (long long)rtop       * W_DIM) + c4);
    v[1] = __ldg((const float4*)(plane + (long long)(rbase    ) * W_DIM) + c4);
    v[2] = __ldg((const float4*)(plane + (long long)(rbase + 1) * W_DIM) + c4);
    v[3] = __ldg((const float4*)(plane + (long long)(rbase + 2) * W_DIM) + c4);
    v[4] = __ldg((const float4*)(plane + (long long)(rbase + 3) * W_DIM) + c4);
    v[5] = __ldg((const float4*)(plane + (long long)rbot        * W_DIM) + c4);

    // horizontal halo via shuffle for the 4 center rows (warps row-aligned).
    int lane = threadIdx.x & 31;
    int c = c4 << 2;
    float lh[4], rh[4];
    #pragma unroll
    for (int i = 0; i < 4; i++) {
        lh[i] = __shfl_up_sync  (0xFFFFFFFFu, v[i + 1].w, 1);
        rh[i] = __shfl_down_sync(0xFFFFFFFFu, v[i + 1].x, 1);
    }
    if (lane == 0) {
        #pragma unroll
        for (int i = 0; i < 4; i++) {
            const float* row = plane + (long long)(rbase + i) * W_DIM;
            lh[i] = (c == 0) ? v[i + 1].x : __ldg(row + c - 1);
        }
    }
    if (lane == 31) {
        #pragma unroll
        for (int i = 0; i < 4; i++) {
            const float* row = plane + (long long)(rbase + i) * W_DIM;
            rh[i] = (c + 4 == W_DIM) ? v[i + 1].w : __ldg(row + c + 4);
        }
    }

    float a0 = __ldg(a + 0), a1 = __ldg(a + 1), a2 = __ldg(a + 2);
    float w0 = __ldg(w + 0), w1 = __ldg(w + 1), w2 = __ldg(w + 2), w3 = __ldg(w + 3);

    float* oplane = out + (long long)p * H_DIM * W_DIM;

    #pragma unroll
    for (int i = 0; i < 4; i++) {
        float4 cv = v[i + 1];
        float4 up = v[i];
        float4 dn = v[i + 2];
        float4 o;

        float xv = cv.x;
        o.x = a0*xv + a1*(lh[i] + cv.y) + a2*(up.x + dn.x)
            + fmaf(fmaf(fmaf(w3, xv, w2), xv, w1), xv, w0);
        xv = cv.y;
        o.y = a0*xv + a1*(cv.x + cv.z) + a2*(up.y + dn.y)
            + fmaf(fmaf(fmaf(w3, xv, w2), xv, w1), xv, w0);
        xv = cv.z;
        o.z = a0*xv + a1*(cv.y + cv.w) + a2*(up.z + dn.z)
            + fmaf(fmaf(fmaf(w3, xv, w2), xv, w1), xv, w0);
        xv = cv.w;
        o.w = a0*xv + a1*(cv.z + rh[i]) + a2*(up.w + dn.w)
            + fmaf(fmaf(fmaf(w3, xv, w2), xv, w1), xv, w0);

        __stcs((float4*)(oplane + (long long)(rbase + i) * W_DIM) + c4, o);
    }
}

extern "C" void kernel_launch(void* const* d_in, const int* in_sizes, int n_in,
                              void* d_out, int out_size)
{
    const float* x = (const float*)d_in[0];
    const float* a = (const float*)d_in[1];
    const float* w = (const float*)d_in[2];
    float* out = (float*)d_out;

    int n = in_sizes[0];
    int nplanes = n / (H_DIM * W_DIM);  // B*C = 16

    long long total = (long long)nplanes * (H_DIM / 4) * (W_DIM / 4);
    int threads = 256;
    long long blocks = (total + threads - 1) / threads;

    stencil_poly_4row<<<(unsigned)blocks, threads>>>(x, a, w, out, nplanes);
}

// round 10
// speedup vs baseline: 1.1986x; 1.0068x over previous
#include <cuda_runtime.h>

// Fused 5-point replicate-pad stencil + cubic Horner polynomial.
// R10: R4 body with block=512 — one CTA covers one full row-quad
// (512 float4 wide x 4 rows). Consecutive CTAs are vertically adjacent
// quads, so halo-row re-reads (rows at quad boundaries) hit L2 from the
// scheduling neighbor. Otherwise identical to the confirmed optimum.

#define H_DIM 2048
#define W_DIM 2048
#define W4    (W_DIM / 4)   // 512
#define HQ    (H_DIM / 4)   // 512 row-quads per plane

__global__ void __launch_bounds__(512) stencil_poly_4row(
    const float* __restrict__ x,
    const float* __restrict__ a,
    const float* __restrict__ w,
    float* __restrict__ out,
    int nplanes)
{
    // blockIdx.x = quad index; quads sweep rows fastest, then planes.
    int rq = blockIdx.x & (HQ - 1);        // row-quad within plane
    int p  = blockIdx.x >> 9;              // / HQ (512)

    int c4 = threadIdx.x;                  // 0..511 (full row)
    int rbase = rq << 2;

    int plane_off = p * (H_DIM * W_DIM);   // < 2^31
    const float* plane = x + plane_off;

    int rtop = (rbase > 0) ? rbase - 1 : 0;
    int rbot = (rbase + 4 < H_DIM) ? rbase + 4 : H_DIM - 1;

    // 6 front-batched row loads: rbase-1 .. rbase+4, clamped.
    float4 v[6];
    v[0] = __ldg((const float4*)(plane + rtop        * W_DIM) + c4);
    v[1] = __ldg((const float4*)(plane + (rbase    ) * W_DIM) + c4);
    v[2] = __ldg((const float4*)(plane + (rbase + 1) * W_DIM) + c4);
    v[3] = __ldg((const float4*)(plane + (rbase + 2) * W_DIM) + c4);
    v[4] = __ldg((const float4*)(plane + (rbase + 3) * W_DIM) + c4);
    v[5] = __ldg((const float4*)(plane + rbot        * W_DIM) + c4);

    // horizontal halo via shuffle (warps row-aligned: 512 % 32 == 0).
    int lane = threadIdx.x & 31;
    int c = c4 << 2;
    float lh[4], rh[4];
    #pragma unroll
    for (int i = 0; i < 4; i++) {
        lh[i] = __shfl_up_sync  (0xFFFFFFFFu, v[i + 1].w, 1);
        rh[i] = __shfl_down_sync(0xFFFFFFFFu, v[i + 1].x, 1);
    }
    if (lane == 0) {
        #pragma unroll
        for (int i = 0; i < 4; i++) {
            const float* row = plane + (rbase + i) * W_DIM;
            lh[i] = (c == 0) ? v[i + 1].x : __ldg(row + c - 1);
        }
    }
    if (lane == 31) {
        #pragma unroll
        for (int i = 0; i < 4; i++) {
            const float* row = plane + (rbase + i) * W_DIM;
            rh[i] = (c + 4 == W_DIM) ? v[i + 1].w : __ldg(row + c + 4);
        }
    }

    float a0 = __ldg(a + 0), a1 = __ldg(a + 1), a2 = __ldg(a + 2);
    float w0 = __ldg(w + 0), w1 = __ldg(w + 1), w2 = __ldg(w + 2), w3 = __ldg(w + 3);

    float* oplane = out + plane_off;

    #pragma unroll
    for (int i = 0; i < 4; i++) {
        float4 cv = v[i + 1];
        float4 up = v[i];
        float4 dn = v[i + 2];
        float4 o;

        float xv = cv.x;
        o.x = a0*xv + a1*(lh[i] + cv.y) + a2*(up.x + dn.x)
            + fmaf(fmaf(fmaf(w3, xv, w2), xv, w1), xv, w0);
        xv = cv.y;
        o.y = a0*xv + a1*(cv.x + cv.z) + a2*(up.y + dn.y)
            + fmaf(fmaf(fmaf(w3, xv, w2), xv, w1), xv, w0);
        xv = cv.z;
        o.z = a0*xv + a1*(cv.y + cv.w) + a2*(up.z + dn.z)
            + fmaf(fmaf(fmaf(w3, xv, w2), xv, w1), xv, w0);
        xv = cv.w;
        o.w = a0*xv + a1*(cv.z + rh[i]) + a2*(up.w + dn.w)
            + fmaf(fmaf(fmaf(w3, xv, w2), xv, w1), xv, w0);

        __stcs((float4*)(oplane + (rbase + i) * W_DIM) + c4, o);
    }
}

extern "C" void kernel_launch(void* const* d_in, const int* in_sizes, int n_in,
                              void* d_out, int out_size)
{
    const float* x = (const float*)d_in[0];
    const float* a = (const float*)d_in[1];
    const float* w = (const float*)d_in[2];
    float* out = (float*)d_out;

    int n = in_sizes[0];
    int nplanes = n / (H_DIM * W_DIM);  // B*C = 16

    int blocks = nplanes * HQ;          // 16 * 512 = 8192 CTAs
    stencil_poly_4row<<<blocks, 512>>>(x, a, w, out, nplanes);
}